// round 5
// baseline (speedup 1.0000x reference)
#include <cuda_runtime.h>
#include <cuda_bf16.h>
#include <cstdint>

#define BDIM 1024
#define KDIM 2048
#define NDIM 4096

// Scratch (device globals — no allocation allowed)
__device__ __nv_bfloat16 g_xb[BDIM * KDIM];   // 2*x in bf16 [1024][2048]
__device__ __nv_bfloat16 g_wb[NDIM * KDIM];   // protos in bf16 [4096][2048]
__device__ float g_xsq[BDIM];
__device__ float g_psq[NDIM];

// ---------------------------------------------------------------------------
// Kernel 1: zero p_sq accumulator
// ---------------------------------------------------------------------------
__global__ void zero_psq_k() {
    int i = blockIdx.x * blockDim.x + threadIdx.x;
    if (i < NDIM) g_psq[i] = 0.0f;
}

// ---------------------------------------------------------------------------
// Kernel 2: pack 2*x -> bf16 (exact: exponent bump), x_sq in fp32.
// ---------------------------------------------------------------------------
__global__ void pack_x_k(const float* __restrict__ x) {
    int row = blockIdx.x;
    int t = threadIdx.x;
    const float4* xr = reinterpret_cast<const float4*>(x + (size_t)row * KDIM);
    float4 v0 = xr[t * 2];
    float4 v1 = xr[t * 2 + 1];
    float s = v0.x*v0.x + v0.y*v0.y + v0.z*v0.z + v0.w*v0.w
            + v1.x*v1.x + v1.y*v1.y + v1.z*v1.z + v1.w*v1.w;

    __nv_bfloat162 o0 = __floats2bfloat162_rn(2.f*v0.x, 2.f*v0.y);
    __nv_bfloat162 o1 = __floats2bfloat162_rn(2.f*v0.z, 2.f*v0.w);
    __nv_bfloat162 o2 = __floats2bfloat162_rn(2.f*v1.x, 2.f*v1.y);
    __nv_bfloat162 o3 = __floats2bfloat162_rn(2.f*v1.z, 2.f*v1.w);
    uint4 pk;
    pk.x = *reinterpret_cast<uint32_t*>(&o0);
    pk.y = *reinterpret_cast<uint32_t*>(&o1);
    pk.z = *reinterpret_cast<uint32_t*>(&o2);
    pk.w = *reinterpret_cast<uint32_t*>(&o3);
    reinterpret_cast<uint4*>(g_xb + (size_t)row * KDIM)[t] = pk;

    #pragma unroll
    for (int off = 16; off; off >>= 1) s += __shfl_xor_sync(0xffffffffu, s, off);
    __shared__ float ws[8];
    if ((t & 31) == 0) ws[t >> 5] = s;
    __syncthreads();
    if (t == 0) {
        float tot = 0.0f;
        #pragma unroll
        for (int j = 0; j < 8; j++) tot += ws[j];
        g_xsq[row] = tot;
    }
}

// ---------------------------------------------------------------------------
// Kernel 3: transpose W [4096,2048] fp32 -> protos bf16 [4096][2048]
// ---------------------------------------------------------------------------
__global__ void pack_w_k(const float* __restrict__ W) {
    __shared__ float tile[32][33];
    __shared__ float sqs[8][32];

    int c0 = blockIdx.x * 32;   // W column
    int r0 = blockIdx.y * 32;   // W row
    int tx = threadIdx.x, ty = threadIdx.y;

    float sq = 0.0f;
    #pragma unroll
    for (int i = 0; i < 4; i++) {
        float v = W[(size_t)(r0 + ty + i * 8) * KDIM + (c0 + tx)];
        tile[ty + i * 8][tx] = v;
        sq += v * v;
    }
    sqs[ty][tx] = sq;
    __syncthreads();

    if (ty == 0) {
        float tot = 0.0f;
        #pragma unroll
        for (int j = 0; j < 8; j++) tot += sqs[j][tx];
        int half = (r0 >= KDIM) ? 1 : 0;
        atomicAdd(&g_psq[2 * (c0 + tx) + half], tot);
    }

    #pragma unroll
    for (int i = 0; i < 4; i++) {
        int c = c0 + ty + i * 8;
        int r = r0 + tx;
        g_wb[(size_t)c * NDIM + r] = __float2bfloat16_rn(tile[tx][ty + i * 8]);
    }
}

// ---------------------------------------------------------------------------
// Kernel 4: GEMM  out[b,o] = sum_k (2x)b[b,k]*wb[o,k] - xsq[b] - psq[o] - bias[o]
// BM=128, BN=256, BK=64, 3-stage cp.async, 256 threads (8 warps, 2Mx4N),
// warp tile 64x64, register double-buffered fragments, LDSM interleaved
// between MMA octets, ONE barrier per 64-K iteration.
// ---------------------------------------------------------------------------
#define BK 64
#define STAGES 3
#define ROWB 144                           // 64 bf16 = 128B + 16B pad
#define A_BYTES (128 * ROWB)               // 18432
#define B_BYTES (256 * ROWB)               // 36864
#define SLOT_BYTES (A_BYTES + B_BYTES)     // 55296
#define TILE_OFF 1024
#define SMEM_TOTAL (TILE_OFF + STAGES * SLOT_BYTES)   // 166912
#define NK2 (KDIM / BK)                    // 32

#define CP16(dst_u32, src_ptr) \
    asm volatile("cp.async.cg.shared.global [%0], [%1], 16;\n" :: "r"(dst_u32), "l"(src_ptr))
#define CP_COMMIT() asm volatile("cp.async.commit_group;\n" ::)
#define CP_WAIT1()  asm volatile("cp.async.wait_group 1;\n" ::)
#define CP_WAIT0()  asm volatile("cp.async.wait_group 0;\n" ::)

#define LDSM_X4(r0, r1, r2, r3, addr) \
    asm volatile("ldmatrix.sync.aligned.m8n8.x4.shared.b16 {%0,%1,%2,%3}, [%4];\n" \
                 : "=r"(r0), "=r"(r1), "=r"(r2), "=r"(r3) : "r"(addr))

#define MMA16816(d, a, b) \
    asm volatile("mma.sync.aligned.m16n8k16.row.col.f32.bf16.bf16.f32 " \
                 "{%0,%1,%2,%3},{%4,%5,%6,%7},{%8,%9},{%0,%1,%2,%3};\n" \
                 : "+f"(d[0]), "+f"(d[1]), "+f"(d[2]), "+f"(d[3]) \
                 : "r"(a[0]), "r"(a[1]), "r"(a[2]), "r"(a[3]), "r"(b[0]), "r"(b[1]))

#define LDSM_A(nb, mi, ax) \
    LDSM_X4(afr[nb][mi][0], afr[nb][mi][1], afr[nb][mi][2], afr[nb][mi][3], \
            (ax) + (uint32_t)((mi) * 16 * ROWB))

#define LDSM_B(nb, nj, bx) do {                                            \
    uint32_t r0_, r1_, r2_, r3_;                                           \
    LDSM_X4(r0_, r1_, r2_, r3_, (bx) + (uint32_t)((nj) * 16 * ROWB));      \
    bfr[nb][2*(nj)][0] = r0_;   bfr[nb][2*(nj)][1] = r1_;                  \
    bfr[nb][2*(nj)+1][0] = r2_; bfr[nb][2*(nj)+1][1] = r3_;                \
} while (0)

#define MMA8(cb, mi) do {                                                  \
    _Pragma("unroll")                                                      \
    for (int ni = 0; ni < 8; ++ni)                                         \
        MMA16816(acc[mi][ni], afr[cb][mi], bfr[cb][ni]);                   \
} while (0)

// one K=16 phase: compute buf cb (32 MMAs), load buf nb from (ax,bx),
// LDSMs threaded between MMA octets
#define PHASE(cb, nb, ax, bx) do {                                         \
    LDSM_A(nb, 0, ax); LDSM_B(nb, 0, bx); LDSM_B(nb, 1, bx);               \
    MMA8(cb, 0);                                                           \
    LDSM_A(nb, 1, ax); LDSM_B(nb, 2, bx);                                  \
    MMA8(cb, 1);                                                           \
    LDSM_A(nb, 2, ax); LDSM_B(nb, 3, bx);                                  \
    MMA8(cb, 2);                                                           \
    LDSM_A(nb, 3, ax);                                                     \
    MMA8(cb, 3);                                                           \
} while (0)

#define PHASE_LAST(cb) do {                                                \
    MMA8(cb, 0); MMA8(cb, 1); MMA8(cb, 2); MMA8(cb, 3);                    \
} while (0)

__global__ void __launch_bounds__(256, 1) gemm_k(const float* __restrict__ bias,
                                                 float* __restrict__ out) {
    extern __shared__ char smem[];
    const uint32_t sb = (uint32_t)__cvta_generic_to_shared(smem);
    float* pbc = reinterpret_cast<float*>(smem);     // [256] psq+bias
    const uint32_t sT = sb + TILE_OFF;

    const int t = threadIdx.x;
    const int bm = blockIdx.y * 128;
    const int bn = blockIdx.x * 256;

    pbc[t] = g_psq[bn + t] + __ldg(&bias[bn + t]);

    const __nv_bfloat16* gA = g_xb + (size_t)bm * KDIM;
    const __nv_bfloat16* gB = g_wb + (size_t)bn * KDIM;

    // loader: rows have 8 16B-chunks. A: 1024 chunks (4/thr), B: 2048 (8/thr)
    auto load_slot = [&](int slot, int k0) {
        uint32_t abase = sT + slot * SLOT_BYTES;
        uint32_t bbase = abase + A_BYTES;
        #pragma unroll
        for (int i = 0; i < 4; i++) {
            int c = t + i * 256;
            int row = c >> 3, col = c & 7;
            CP16(abase + (uint32_t)(row * ROWB + col * 16),
                 gA + (size_t)row * KDIM + k0 + col * 8);
        }
        #pragma unroll
        for (int i = 0; i < 8; i++) {
            int c = t + i * 256;
            int row = c >> 3, col = c & 7;
            CP16(bbase + (uint32_t)(row * ROWB + col * 16),
                 gB + (size_t)row * KDIM + k0 + col * 8);
        }
    };

    const int warp = t >> 5, lane = t & 31;
    const int wm = warp & 1;   // 2 x 64 rows
    const int wn = warp >> 1;  // 4 x 64 cols

    const uint32_t aoff = (uint32_t)((wm * 64 + (lane & 15)) * ROWB + (lane >> 4) * 16);
    const uint32_t boff = (uint32_t)((wn * 64 + (lane & 7) + ((lane & 16) >> 1)) * ROWB
                                     + ((lane >> 3) & 1) * 16);

    float acc[4][8][4] = {};
    uint32_t afr[2][4][4];
    uint32_t bfr[2][8][2];

    // prologue: 2 stages in flight
    load_slot(0, 0);  CP_COMMIT();
    load_slot(1, BK); CP_COMMIT();
    CP_WAIT1();
    __syncthreads();

    // preload buf0 <- (stage0, ks0)
    {
        const uint32_t ax = sT + aoff;
        const uint32_t bx = sT + A_BYTES + boff;
        LDSM_A(0, 0, ax); LDSM_A(0, 1, ax); LDSM_A(0, 2, ax); LDSM_A(0, 3, ax);
        LDSM_B(0, 0, bx); LDSM_B(0, 1, bx); LDSM_B(0, 2, bx); LDSM_B(0, 3, bx);
    }

    for (int kt = 0; kt < NK2; ++kt) {
        const uint32_t sAs = sT + (kt % STAGES) * SLOT_BYTES;
        const uint32_t ax = sAs + aoff;
        const uint32_t bx = sAs + A_BYTES + boff;

        // ks0: compute buf0, load buf1 <- ks1
        PHASE(0, 1, ax + 32, bx + 32);

        // issue next-slot global loads (slot (kt+2)%3 == (kt-1)%3, free since
        // the barrier inside iteration kt-1)
        if (kt + 2 < NK2) load_slot((kt + 2) % STAGES, (kt + 2) * BK);
        CP_COMMIT();

        // ks1: compute buf1, load buf0 <- ks2
        PHASE(1, 0, ax + 64, bx + 64);
        // ks2: compute buf0, load buf1 <- ks3
        PHASE(0, 1, ax + 96, bx + 96);

        // ks3: compute buf1, load buf0 <- (kt+1, ks0) after wait+sync
        if (kt + 1 < NK2) {
            if (kt < NK2 - 2) { CP_WAIT1(); } else { CP_WAIT0(); }
            __syncthreads();
            const uint32_t nAs = sT + ((kt + 1) % STAGES) * SLOT_BYTES;
            PHASE(1, 0, nAs + aoff, nAs + A_BYTES + boff);
        } else {
            PHASE_LAST(1);
        }
    }

    // epilogue: out = acc - xsq[row] - (psq+bias)[col]
    const int gid = lane >> 2, qid = lane & 3;
    #pragma unroll
    for (int mi = 0; mi < 4; ++mi) {
        int row0 = bm + wm * 64 + mi * 16 + gid;
        float xs0 = g_xsq[row0];
        float xs1 = g_xsq[row0 + 8];
        #pragma unroll
        for (int ni = 0; ni < 8; ++ni) {
            int lc = wn * 64 + ni * 8 + qid * 2;
            float pb0 = pbc[lc];
            float pb1 = pbc[lc + 1];
            float2 v0, v1;
            v0.x = acc[mi][ni][0] - xs0 - pb0;
            v0.y = acc[mi][ni][1] - xs0 - pb1;
            v1.x = acc[mi][ni][2] - xs1 - pb0;
            v1.y = acc[mi][ni][3] - xs1 - pb1;
            *reinterpret_cast<float2*>(out + (size_t)row0 * NDIM + bn + lc) = v0;
            *reinterpret_cast<float2*>(out + (size_t)(row0 + 8) * NDIM + bn + lc) = v1;
        }
    }
}

// ---------------------------------------------------------------------------
extern "C" void kernel_launch(void* const* d_in, const int* in_sizes, int n_in,
                              void* d_out, int out_size) {
    const float* x    = (const float*)d_in[0];
    const float* W    = (const float*)d_in[1];
    const float* bias = (const float*)d_in[2];
    float* out = (float*)d_out;

    cudaFuncSetAttribute(gemm_k, cudaFuncAttributeMaxDynamicSharedMemorySize, SMEM_TOTAL);

    zero_psq_k<<<NDIM / 256, 256>>>();
    pack_x_k<<<BDIM, 256>>>(x);
    pack_w_k<<<dim3(KDIM / 32, NDIM / 32), dim3(32, 8)>>>(W);
    gemm_k<<<dim3(NDIM / 256, BDIM / 128), 256, SMEM_TOTAL>>>(bias, out);
}